// round 5
// baseline (speedup 1.0000x reference)
#include <cuda_runtime.h>

#define W56   56
#define HW    3136
#define WC_N  32
#define C_N   256
#define GRP   8
#define NTHR  256
#define W4N   14               // float4 per row
#define P4    (W56 * W4N)      // 784 float4-pixels per (b,c) image

__device__ __forceinline__ float4 zf4() { return make_float4(0.f, 0.f, 0.f, 0.f); }

template<int I>
__device__ __forceinline__ float comp(const float4& v) {
    if constexpr (I == 0) return v.x;
    else if constexpr (I == 1) return v.y;
    else if constexpr (I == 2) return v.z;
    else return v.w;
}
// 12-wide window [L|M|R], index 0..11
template<int IDX>
__device__ __forceinline__ float sel(const float4& L, const float4& M, const float4& R) {
    if constexpr (IDX < 4)      return comp<IDX>(L);
    else if constexpr (IDX < 8) return comp<IDX - 4>(M);
    else                        return comp<IDX - 8>(R);
}

template<int D, int KW>
__device__ __forceinline__ void fma4(float4& acc, const float4& wk,
                                     const float4& L, const float4& M, const float4& R) {
    constexpr int c = (KW - 1) * D;
    acc.x += wk.x * sel<4 + 0 + c>(L, M, R);
    acc.y += wk.y * sel<4 + 1 + c>(L, M, R);
    acc.z += wk.z * sel<4 + 2 + c>(L, M, R);
    acc.w += wk.w * sel<4 + 3 + c>(L, M, R);
}

template<int D>
__device__ __forceinline__ void lcd_body(const float* __restrict__ x,
                                         float* __restrict__ out,
                                         const float4* __restrict__ wsm,  // &wsm[0][tid], stride NTHR
                                         int bc, int h, int w4)
{
    const bool lv = (w4 > 0), rvx = (w4 < 52);
    bool  rv[3];
    int   roff[3];
#pragma unroll
    for (int j = 0; j < 3; j++) {
        const int hh = h + (j - 1) * D;
        rv[j]   = (unsigned)hh < (unsigned)W56;
        roff[j] = hh * W56 + w4;
    }

    const float* xb = x   + (size_t)bc * HW;
    float*       ob = out + (size_t)bc * HW + h * W56 + w4;

#pragma unroll 1
    for (int g = 0; g < GRP; g += 2) {
        const float* xp0 = xb + (size_t)g * WC_N * HW;
        const float* xp1 = xp0 + (size_t)WC_N * HW;
        float4 acc0 = zf4(), acc1 = zf4();
#pragma unroll
        for (int j = 0; j < 3; j++) {
            const bool v = rv[j];
            const float* r0 = xp0 + roff[j];
            const float* r1 = xp1 + roff[j];
            float4 L0 = (v && lv)  ? *(const float4*)(r0 - 4) : zf4();
            float4 M0 =  v         ? *(const float4*)(r0)     : zf4();
            float4 R0 = (v && rvx) ? *(const float4*)(r0 + 4) : zf4();
            float4 L1 = (v && lv)  ? *(const float4*)(r1 - 4) : zf4();
            float4 M1 =  v         ? *(const float4*)(r1)     : zf4();
            float4 R1 = (v && rvx) ? *(const float4*)(r1 + 4) : zf4();
            {
                float4 wk = wsm[(j * 3 + 0) * NTHR];
                fma4<D, 0>(acc0, wk, L0, M0, R0);
                fma4<D, 0>(acc1, wk, L1, M1, R1);
            }
            {
                float4 wk = wsm[(j * 3 + 1) * NTHR];
                fma4<D, 1>(acc0, wk, L0, M0, R0);
                fma4<D, 1>(acc1, wk, L1, M1, R1);
            }
            {
                float4 wk = wsm[(j * 3 + 2) * NTHR];
                fma4<D, 2>(acc0, wk, L0, M0, R0);
                fma4<D, 2>(acc1, wk, L1, M1, R1);
            }
        }
        *(float4*)(ob + (size_t)g * WC_N * HW)       = acc0;
        *(float4*)(ob + (size_t)(g + 1) * WC_N * HW) = acc1;
    }
}

__global__ __launch_bounds__(NTHR, 5)
void lcd_kernel(const float* __restrict__ x,
                const float* __restrict__ weight,
                const int*   __restrict__ dilation,
                float*       __restrict__ out)
{
    __shared__ float4 wsm[9][NTHR];   // per-thread weight slot, 36 KB

    const int tid = threadIdx.x;
    const int idx = blockIdx.x * NTHR + tid;       // 0..25087 = wc*784 + p4
    const int b   = blockIdx.y;
    const int wc  = idx / P4;
    const int p4i = idx - wc * P4;
    const int h   = p4i / W4N;
    const int w4  = (p4i - h * W4N) * 4;
    const int bc  = b * C_N + wc;

    // stage this thread's 9 float4 weights into smem (own slot: no sync needed)
    {
        const float* wp = weight + ((size_t)(b * WC_N + wc) * 9) * HW + h * W56 + w4;
#pragma unroll
        for (int k = 0; k < 9; k++) wsm[k][tid] = *(const float4*)(wp + k * HW);
    }

    const int d = __ldg(&dilation[wc]);   // 1..4
    const float4* ws = &wsm[0][tid];

    switch (d) {
        case 1:  lcd_body<1>(x, out, ws, bc, h, w4); break;
        case 2:  lcd_body<2>(x, out, ws, bc, h, w4); break;
        case 3:  lcd_body<3>(x, out, ws, bc, h, w4); break;
        default: lcd_body<4>(x, out, ws, bc, h, w4); break;
    }
}

extern "C" void kernel_launch(void* const* d_in, const int* in_sizes, int n_in,
                              void* d_out, int out_size)
{
    const float* x        = (const float*)d_in[0];
    const float* weight   = (const float*)d_in[1];
    const int*   dilation = (const int*)d_in[2];
    float*       out      = (float*)d_out;

    dim3 grid((WC_N * P4) / NTHR, 8);   // (98, 8) — exact cover, no tail
    dim3 block(NTHR);
    lcd_kernel<<<grid, block>>>(x, weight, dilation, out);
}

// round 7
// speedup vs baseline: 2.6958x; 2.6958x over previous
#include <cuda_runtime.h>

#define W56   56
#define HW    3136
#define WC_N  32
#define C_N   256
#define GRP   8
#define NTHR  256
#define W4N   14               // float4 per row
#define P4    (W56 * W4N)      // 784 float4-pixels per (b,c) image

__device__ __forceinline__ float4 zf4() { return make_float4(0.f, 0.f, 0.f, 0.f); }

template<int I>
__device__ __forceinline__ float comp(const float4& v) {
    if constexpr (I == 0) return v.x;
    else if constexpr (I == 1) return v.y;
    else if constexpr (I == 2) return v.z;
    else return v.w;
}
// 12-wide window [L|M|R], index 0..11
template<int IDX>
__device__ __forceinline__ float sel(const float4& L, const float4& M, const float4& R) {
    if constexpr (IDX < 4)      return comp<IDX>(L);
    else if constexpr (IDX < 8) return comp<IDX - 4>(M);
    else                        return comp<IDX - 8>(R);
}

template<int D, int KW>
__device__ __forceinline__ void fma4(float4& acc, const float4& wk,
                                     const float4& L, const float4& M, const float4& R) {
    constexpr int c = (KW - 1) * D;
    acc.x += wk.x * sel<4 + 0 + c>(L, M, R);
    acc.y += wk.y * sel<4 + 1 + c>(L, M, R);
    acc.z += wk.z * sel<4 + 2 + c>(L, M, R);
    acc.w += wk.w * sel<4 + 3 + c>(L, M, R);
}

template<int D>
__device__ __forceinline__ void lcd_body(const float* __restrict__ x,
                                         const float* __restrict__ weight,
                                         float* __restrict__ out,
                                         int b, int wc, int h, int w4)
{
    // 9 taps × 4 pixels of weights in registers, reused across all 8 channel groups
    float4 wg[9];
    {
        const float* wp = weight + ((size_t)(b * WC_N + wc) * 9) * HW + h * W56 + w4;
#pragma unroll
        for (int k = 0; k < 9; k++) wg[k] = *(const float4*)(wp + k * HW);
    }

    const bool lv = (w4 > 0), rvx = (w4 < 52);
    bool rv[3];
    int  roff[3];
#pragma unroll
    for (int j = 0; j < 3; j++) {
        const int hh = h + (j - 1) * D;
        rv[j]   = (unsigned)hh < (unsigned)W56;
        roff[j] = hh * W56 + w4;
    }

    const float* xb = x   + (size_t)(b * C_N + wc) * HW;
    float*       ob = out + (size_t)(b * C_N + wc) * HW + h * W56 + w4;

#pragma unroll 1
    for (int g = 0; g < GRP; g += 2) {
        const float* xp0 = xb + (size_t)g * WC_N * HW;
        const float* xp1 = xp0 + (size_t)WC_N * HW;
        float4 acc0 = zf4(), acc1 = zf4();
        // front-batch all 18 independent loads for max MLP
        float4 L[2][3], M[2][3], R[2][3];
#pragma unroll
        for (int j = 0; j < 3; j++) {
            const bool v = rv[j];
            const float* r0 = xp0 + roff[j];
            const float* r1 = xp1 + roff[j];
            L[0][j] = (v && lv)  ? *(const float4*)(r0 - 4) : zf4();
            M[0][j] =  v         ? *(const float4*)(r0)     : zf4();
            R[0][j] = (v && rvx) ? *(const float4*)(r0 + 4) : zf4();
            L[1][j] = (v && lv)  ? *(const float4*)(r1 - 4) : zf4();
            M[1][j] =  v         ? *(const float4*)(r1)     : zf4();
            R[1][j] = (v && rvx) ? *(const float4*)(r1 + 4) : zf4();
        }
#pragma unroll
        for (int j = 0; j < 3; j++) {
            fma4<D, 0>(acc0, wg[j * 3 + 0], L[0][j], M[0][j], R[0][j]);
            fma4<D, 1>(acc0, wg[j * 3 + 1], L[0][j], M[0][j], R[0][j]);
            fma4<D, 2>(acc0, wg[j * 3 + 2], L[0][j], M[0][j], R[0][j]);
            fma4<D, 0>(acc1, wg[j * 3 + 0], L[1][j], M[1][j], R[1][j]);
            fma4<D, 1>(acc1, wg[j * 3 + 1], L[1][j], M[1][j], R[1][j]);
            fma4<D, 2>(acc1, wg[j * 3 + 2], L[1][j], M[1][j], R[1][j]);
        }
        *(float4*)(ob + (size_t)g * WC_N * HW)       = acc0;
        *(float4*)(ob + (size_t)(g + 1) * WC_N * HW) = acc1;
    }
}

__global__ __launch_bounds__(NTHR)
void lcd_kernel(const float* __restrict__ x,
                const float* __restrict__ weight,
                const int*   __restrict__ dilation,
                float*       __restrict__ out)
{
    const int idx = blockIdx.x * NTHR + threadIdx.x;  // wc*784 + p4, exact cover
    const int b   = blockIdx.y;
    const int wc  = idx / P4;
    const int p4i = idx - wc * P4;
    const int h   = p4i / W4N;
    const int w4  = (p4i - h * W4N) * 4;
    const int d   = __ldg(&dilation[wc]);   // 1..4

    switch (d) {
        case 1:  lcd_body<1>(x, weight, out, b, wc, h, w4); break;
        case 2:  lcd_body<2>(x, weight, out, b, wc, h, w4); break;
        case 3:  lcd_body<3>(x, weight, out, b, wc, h, w4); break;
        default: lcd_body<4>(x, weight, out, b, wc, h, w4); break;
    }
}

extern "C" void kernel_launch(void* const* d_in, const int* in_sizes, int n_in,
                              void* d_out, int out_size)
{
    const float* x        = (const float*)d_in[0];
    const float* weight   = (const float*)d_in[1];
    const int*   dilation = (const int*)d_in[2];
    float*       out      = (float*)d_out;

    dim3 grid((WC_N * P4) / NTHR, 8);   // (98, 8) — exact cover, no tail
    dim3 block(NTHR);
    lcd_kernel<<<grid, block>>>(x, weight, dilation, out);
}